// round 6
// baseline (speedup 1.0000x reference)
#include <cuda_runtime.h>
#include <cstdint>

// ---------------------------------------------------------------------------
// HierarchUpdateMlp — legacy mma.sync tf32 (tcgen05 not available: harness
// compiles PTX at .target sm_103, no 'a' features).
//   prepass : rna-round all weights into scratch
//   k<0>    : stage A, 7 GEMMs (CTA 256x128, K=1280/512) -> g_out1
//   k<1>    : stage B, 6 GEMMs (CTA 256x128, K=256, pair gather) -> g_out2
//   k<2>    : stage C, GEMM (CTA 128x256, K=768) -> out
// 4-stage cp.async ring, ONE barrier per 32-K chunk, register-double-buffered
// fragments, stride-36 padded smem (conflict-free fragment LDS).
// ---------------------------------------------------------------------------

#define NPAD 50176  // ceil(50000/256)*256

__device__ __align__(16) float g_out1[(size_t)NPAD * 896];
__device__ __align__(16) float g_out2[(size_t)NPAD * 768];
__device__ __align__(16) float g_W10r[128 * 1280];
__device__ __align__(16) float g_W1r[6 * 128 * 512];
__device__ __align__(16) float g_W2r[6 * 128 * 256];
__device__ __align__(16) float g_Wfr[256 * 768];

#define STG_FLTS 13824          // (AM+BN)*36, same for both tilings
#define STG_BYTES (STG_FLTS * 4)

__device__ __forceinline__ float f2tff(float x) {
    unsigned u;
    asm("cvt.rna.tf32.f32 %0, %1;" : "=r"(u) : "f"(x));
    return __uint_as_float(u);
}
__device__ __forceinline__ uint32_t smaddr(const void* p) {
    uint32_t a;
    asm("{ .reg .u64 t; cvta.to.shared.u64 t, %1; cvt.u32.u64 %0, t; }"
        : "=r"(a) : "l"(p));
    return a;
}
__device__ __forceinline__ void cpa_cg(uint32_t d, const float* s) {
    asm volatile("cp.async.cg.shared.global [%0], [%1], 16;" :: "r"(d), "l"(s)
                 : "memory");
}
__device__ __forceinline__ void cp_commit() {
    asm volatile("cp.async.commit_group;" ::: "memory");
}
__device__ __forceinline__ void cp_wait(int allowed) {
    if (allowed >= 2) asm volatile("cp.async.wait_group 2;" ::: "memory");
    else if (allowed == 1) asm volatile("cp.async.wait_group 1;" ::: "memory");
    else asm volatile("cp.async.wait_group 0;" ::: "memory");
}
__device__ __forceinline__ void mma8(float (&c)[4], const unsigned (&a)[4],
                                     const unsigned (&b)[2]) {
    asm volatile(
        "mma.sync.aligned.m16n8k8.row.col.f32.tf32.tf32.f32 "
        "{%0,%1,%2,%3},{%4,%5,%6,%7},{%8,%9},{%0,%1,%2,%3};\n"
        : "+f"(c[0]), "+f"(c[1]), "+f"(c[2]), "+f"(c[3])
        : "r"(a[0]), "r"(a[1]), "r"(a[2]), "r"(a[3]), "r"(b[0]), "r"(b[1]));
}

// ---------------------------------------------------------------------------
__global__ void round_weights_kernel(const float* __restrict__ W10,
                                     const float* __restrict__ W1,
                                     const float* __restrict__ W2,
                                     const float* __restrict__ Wf) {
    int i = blockIdx.x * blockDim.x + threadIdx.x;
    int st = gridDim.x * blockDim.x;
    for (int j = i; j < 128 * 1280; j += st) g_W10r[j] = f2tff(W10[j]);
    for (int j = i; j < 6 * 128 * 512; j += st) g_W1r[j] = f2tff(W1[j]);
    for (int j = i; j < 6 * 128 * 256; j += st) g_W2r[j] = f2tff(W2[j]);
    for (int j = i; j < 256 * 768; j += st) g_Wfr[j] = f2tff(Wf[j]);
}

// ---------------------------------------------------------------------------
// Unified GEMM. MODE 0/1: CTA 256x128 (warps 4m x 2n). MODE 2: CTA 128x256
// (warps 2m x 4n). Warp tile 64x64 everywhere; acc[4][8][4].
// ---------------------------------------------------------------------------
template <int MODE>
__global__ __launch_bounds__(256, 1)
void gemm_k(const float* __restrict__ Ain, const float* __restrict__ bias0,
            const float* __restrict__ bias1, float* __restrict__ dstp, int N) {
    extern __shared__ __align__(16) float sm[];

    constexpr int AM = (MODE == 2) ? 128 : 256;  // A rows per CTA
    constexpr int BN = (MODE == 2) ? 256 : 128;  // B rows (= output cols)

    const int tid = threadIdx.x;
    const int lane = tid & 31, warp = tid >> 5;
    const int wm = (MODE == 2) ? (warp >> 2) : (warp >> 1);
    const int wn = (MODE == 2) ? (warp & 3) : (warp & 1);
    const int qr = lane >> 2, qc = lane & 3;
    const int row0 = blockIdx.x * AM;
    const int g = blockIdx.y;

    int K, ldB, ldA, ldO, colO, j1 = 0, j2 = 0, c1 = 0, c2 = 0;
    const float *Bsrc, *bias, *Asrc;
    float* Dst;
    if (MODE == 0) {
        if (g == 0) { K = 1280; Bsrc = g_W10r; ldB = 1280; bias = bias0; }
        else {
            const int p1[6] = {5, 7, 8, 11, 13, 14};
            const int p2[6] = {6, 9, 10, 12, 15, 16};
            K = 512; Bsrc = g_W1r + (size_t)(g - 1) * 65536; ldB = 512;
            bias = bias1 + (g - 1) * 128;
            j1 = p1[g - 1]; j2 = p2[g - 1];
        }
        Asrc = Ain; ldA = 4352; Dst = g_out1; ldO = 896; colO = g * 128;
    } else if (MODE == 1) {
        const int q1[6] = {0, 1, 1, 1, 4, 4};
        const int q2[6] = {1, 2, 3, 4, 5, 6};
        K = 256; Bsrc = g_W2r + (size_t)g * 32768; ldB = 256;
        bias = bias0 + g * 128;
        c1 = q1[g] * 128; c2 = q2[g] * 128;
        Asrc = g_out1; ldA = 896; Dst = g_out2; ldO = 768; colO = g * 128;
    } else {
        K = 768; Bsrc = g_Wfr; ldB = 768;
        bias = bias0;
        Asrc = g_out2; ldA = 768; Dst = dstp; ldO = 256; colO = 0;
    }
    const int nk = K >> 5;

    float acc[4][8][4];
#pragma unroll
    for (int i = 0; i < 4; i++)
#pragma unroll
        for (int j = 0; j < 8; j++)
#pragma unroll
            for (int k = 0; k < 4; k++) acc[i][j][k] = 0.f;

    const uint32_t smb = smaddr(sm);

    auto issue = [&](int ci) {
        const int k0 = ci * 32;
        const uint32_t Ab = smb + (uint32_t)(ci & 3) * STG_BYTES;
        const uint32_t Bb = Ab + (uint32_t)AM * 36 * 4;
        int joff;
        if (MODE == 0)
            joff = (g == 0) ? k0 : (((k0 < 256) ? j1 : j2) * 256 + (k0 & 255));
        else if (MODE == 1)
            joff = (k0 < 128) ? (c1 + k0) : (c2 + k0 - 128);
        else
            joff = k0;
#pragma unroll
        for (int u = 0; u < AM / 32; u++) {
            const int idx = tid + u * 256, row = idx >> 3, seg = idx & 7;
            int r = row0 + row;
            if (r > N - 1) r = N - 1;
            cpa_cg(Ab + (uint32_t)(row * 36 + seg * 4) * 4,
                   Asrc + (size_t)r * ldA + joff + seg * 4);
        }
#pragma unroll
        for (int u = 0; u < BN / 32; u++) {
            const int idx = tid + u * 256, row = idx >> 3, seg = idx & 7;
            cpa_cg(Bb + (uint32_t)(row * 36 + seg * 4) * 4,
                   Bsrc + (size_t)row * ldB + k0 + seg * 4);
        }
        cp_commit();
    };

    issue(0); issue(1); issue(2);

    for (int i = 0; i < nk; i++) {
        const int rem = nk - 1 - i;
        cp_wait(rem < 2 ? rem : 2);
        __syncthreads();               // stage i visible AND slot (i+3)&3 free
        if (i + 3 < nk) issue(i + 3);

        const float* As = sm + (i & 3) * STG_FLTS;
        const float* Bs = As + AM * 36;

        unsigned a[2][4][4], b[2][8][2];
        auto loadfrag = [&](int k8, unsigned (&aa)[4][4], unsigned (&bb)[8][2]) {
            const int kk = k8 * 8;
#pragma unroll
            for (int mt = 0; mt < 4; mt++) {
                const int r = wm * 64 + mt * 16 + qr;
                float a0 = As[r * 36 + kk + qc];
                float a1 = As[(r + 8) * 36 + kk + qc];
                float a2 = As[r * 36 + kk + qc + 4];
                float a3 = As[(r + 8) * 36 + kk + qc + 4];
                if (MODE == 0) {
                    a0 = f2tff(a0); a1 = f2tff(a1);
                    a2 = f2tff(a2); a3 = f2tff(a3);
                }
                aa[mt][0] = __float_as_uint(a0);
                aa[mt][1] = __float_as_uint(a1);
                aa[mt][2] = __float_as_uint(a2);
                aa[mt][3] = __float_as_uint(a3);
            }
#pragma unroll
            for (int nt = 0; nt < 8; nt++) {
                const int n = wn * 64 + nt * 8 + qr;
                bb[nt][0] = __float_as_uint(Bs[n * 36 + kk + qc]);
                bb[nt][1] = __float_as_uint(Bs[n * 36 + kk + qc + 4]);
            }
        };

        loadfrag(0, a[0], b[0]);
#pragma unroll
        for (int k8 = 0; k8 < 4; k8++) {
            const int cur = k8 & 1;
            if (k8 < 3) loadfrag(k8 + 1, a[cur ^ 1], b[cur ^ 1]);
#pragma unroll
            for (int mt = 0; mt < 4; mt++)
#pragma unroll
                for (int nt = 0; nt < 8; nt++)
                    mma8(acc[mt][nt], a[cur][mt], b[cur][nt]);
        }
    }

    // Epilogue: bias + relu (+rna for intermediates), direct STG.
#pragma unroll
    for (int mt = 0; mt < 4; mt++) {
        const int r0 = row0 + wm * 64 + mt * 16 + qr;
#pragma unroll
        for (int nt = 0; nt < 8; nt++) {
            const int lc = wn * 64 + nt * 8 + 2 * qc;
            const float bb0 = __ldg(bias + lc);
            const float bb1 = __ldg(bias + lc + 1);
            float v0 = fmaxf(acc[mt][nt][0] + bb0, 0.f);
            float v1 = fmaxf(acc[mt][nt][1] + bb1, 0.f);
            float v2 = fmaxf(acc[mt][nt][2] + bb0, 0.f);
            float v3 = fmaxf(acc[mt][nt][3] + bb1, 0.f);
            if (MODE < 2) {
                v0 = f2tff(v0); v1 = f2tff(v1); v2 = f2tff(v2); v3 = f2tff(v3);
            }
            if (r0 < N)
                *(float2*)&Dst[(size_t)r0 * ldO + colO + lc] = make_float2(v0, v1);
            if (r0 + 8 < N)
                *(float2*)&Dst[(size_t)(r0 + 8) * ldO + colO + lc] =
                    make_float2(v2, v3);
        }
    }
}

// ---------------------------------------------------------------------------
extern "C" void kernel_launch(void* const* d_in, const int* in_sizes, int n_in,
                              void* d_out, int out_size) {
    const float* upd = (const float*)d_in[0];
    const float* W10 = (const float*)d_in[1];
    const float* b10 = (const float*)d_in[2];
    const float* W1  = (const float*)d_in[3];
    const float* b1  = (const float*)d_in[4];
    const float* W2  = (const float*)d_in[5];
    const float* b2  = (const float*)d_in[6];
    const float* Wf  = (const float*)d_in[7];
    const float* bf  = (const float*)d_in[8];
    const int N = in_sizes[0] / (17 * 256);

    const int smem = 4 * STG_BYTES;  // 221184 B
    cudaFuncSetAttribute(gemm_k<0>, cudaFuncAttributeMaxDynamicSharedMemorySize, smem);
    cudaFuncSetAttribute(gemm_k<1>, cudaFuncAttributeMaxDynamicSharedMemorySize, smem);
    cudaFuncSetAttribute(gemm_k<2>, cudaFuncAttributeMaxDynamicSharedMemorySize, smem);

    round_weights_kernel<<<256, 256>>>(W10, W1, W2, Wf);

    const int t256 = (N + 255) / 256;
    const int t128 = (N + 127) / 128;
    gemm_k<0><<<dim3(t256, 7), 256, smem>>>(upd, b10, b1, nullptr, N);
    gemm_k<1><<<dim3(t256, 6), 256, smem>>>(nullptr, b2, nullptr, nullptr, N);
    gemm_k<2><<<dim3(t128, 1), 256, smem>>>(nullptr, bf, nullptr, (float*)d_out, N);
}

// round 7
// speedup vs baseline: 1.5207x; 1.5207x over previous
#include <cuda_runtime.h>
#include <cuda_fp16.h>
#include <cstdint>

// ---------------------------------------------------------------------------
// HierarchUpdateMlp — fp16 mma.sync m16n8k16 with fp32 accumulation.
// fp16 mantissa (10 bits) == tf32 mantissa -> same rounding error as the
// tf32 version (measured 4.7e-4), but 2048 MACs/instruction instead of 1024.
//   prepass : convert all weights to fp16 scratch
//   k<0>    : stage A, 7 GEMMs (CTA 256x128, K=1280/512) -> g_out1h (fp16)
//   k<1>    : stage B, 6 GEMMs (CTA 256x128, K=256, pair gather) -> g_out2h
//   k<2>    : stage C, GEMM  (CTA 128x256, K=768) -> out (fp32)
// Smem: stride-20-b32 rows (20r mod 32 covers all banks over 8 rows) ->
// conflict-free m16n8k16 fragment loads. K-chunk 32.
// ---------------------------------------------------------------------------

#define NPAD 50176  // = ceil(50000/256)*256

__device__ __align__(16) __half g_out1h[(size_t)NPAD * 896];
__device__ __align__(16) __half g_out2h[(size_t)NPAD * 768];
__device__ __align__(16) __half g_W10h[128 * 1280];
__device__ __align__(16) __half g_W1h[6 * 128 * 512];
__device__ __align__(16) __half g_W2h[6 * 128 * 256];
__device__ __align__(16) __half g_Wfh[256 * 768];

#define STG_U32 7680           // (AM+BN)*20 = 384*20 u32 per stage
#define STG_BYTES (STG_U32 * 4)  // 30720 B

__device__ __forceinline__ uint32_t smaddr(const void* p) {
    uint32_t a;
    asm("{ .reg .u64 t; cvta.to.shared.u64 t, %1; cvt.u32.u64 %0, t; }"
        : "=r"(a) : "l"(p));
    return a;
}
__device__ __forceinline__ uint32_t packh(float hi, float lo) {
    uint32_t r;
    asm("cvt.rn.f16x2.f32 %0, %1, %2;" : "=r"(r) : "f"(hi), "f"(lo));
    return r;
}
__device__ __forceinline__ void cpa_cg(uint32_t d, const void* s) {
    asm volatile("cp.async.cg.shared.global [%0], [%1], 16;" :: "r"(d), "l"(s)
                 : "memory");
}
__device__ __forceinline__ void cp_commit() {
    asm volatile("cp.async.commit_group;" ::: "memory");
}
__device__ __forceinline__ void cp_wait(int allowed) {
    if (allowed >= 2) asm volatile("cp.async.wait_group 2;" ::: "memory");
    else if (allowed == 1) asm volatile("cp.async.wait_group 1;" ::: "memory");
    else asm volatile("cp.async.wait_group 0;" ::: "memory");
}
__device__ __forceinline__ void sts64(uint32_t a, uint32_t x, uint32_t y) {
    asm volatile("st.shared.v2.b32 [%0], {%1,%2};" :: "r"(a), "r"(x), "r"(y)
                 : "memory");
}
__device__ __forceinline__ void mma16(float (&c)[4], const unsigned (&a)[4],
                                      const unsigned (&b)[2]) {
    asm volatile(
        "mma.sync.aligned.m16n8k16.row.col.f32.f16.f16.f32 "
        "{%0,%1,%2,%3},{%4,%5,%6,%7},{%8,%9},{%0,%1,%2,%3};\n"
        : "+f"(c[0]), "+f"(c[1]), "+f"(c[2]), "+f"(c[3])
        : "r"(a[0]), "r"(a[1]), "r"(a[2]), "r"(a[3]), "r"(b[0]), "r"(b[1]));
}

// ---------------------------------------------------------------------------
__global__ void cvt_weights(const float* __restrict__ W10,
                            const float* __restrict__ W1,
                            const float* __restrict__ W2,
                            const float* __restrict__ Wf) {
    int i = blockIdx.x * blockDim.x + threadIdx.x;
    int st = gridDim.x * blockDim.x;
    for (int j = i; j < 128 * 1280; j += st) g_W10h[j] = __float2half_rn(W10[j]);
    for (int j = i; j < 6 * 128 * 512; j += st) g_W1h[j] = __float2half_rn(W1[j]);
    for (int j = i; j < 6 * 128 * 256; j += st) g_W2h[j] = __float2half_rn(W2[j]);
    for (int j = i; j < 256 * 768; j += st) g_Wfh[j] = __float2half_rn(Wf[j]);
}

// ---------------------------------------------------------------------------
// MODE 0: A=update fp32 (LDG->cvt->STS, 2-stage), B weights fp16, out fp16
// MODE 1: A=g_out1h fp16 (cp.async, 4-stage),     B=g_W2h,       out fp16
// MODE 2: A=g_out2h fp16 (cp.async, 4-stage),     B=g_Wfh,       out fp32
// ---------------------------------------------------------------------------
template <int MODE>
__global__ __launch_bounds__(256, 1)
void gemm_h(const float* __restrict__ Aupd, const float* __restrict__ bias0,
            const float* __restrict__ bias1, float* __restrict__ outp, int N) {
    extern __shared__ __align__(16) uint32_t smu[];

    constexpr int AM = (MODE == 2) ? 128 : 256;
    constexpr int BN = (MODE == 2) ? 256 : 128;

    const int tid = threadIdx.x;
    const int lane = tid & 31, warp = tid >> 5;
    const int wm = (MODE == 2) ? (warp >> 2) : (warp >> 1);
    const int wn = (MODE == 2) ? (warp & 3) : (warp & 1);
    const int qr = lane >> 2, qc = lane & 3;
    const int row0 = blockIdx.x * AM;
    const int g = blockIdx.y;
    const uint32_t smb = smaddr(smu);

    int K, ldB, j1 = 0, j2 = 0, c1 = 0, c2 = 0;
    const __half* Bsrc;
    const float* bias;
    const __half* Ah = nullptr;
    int ldA = 0, ldO, colO;
    __half* Dh = nullptr;
    if (MODE == 0) {
        if (g == 0) { K = 1280; Bsrc = g_W10h; ldB = 1280; bias = bias0; }
        else {
            const int p1[6] = {5, 7, 8, 11, 13, 14};
            const int p2[6] = {6, 9, 10, 12, 15, 16};
            K = 512; Bsrc = g_W1h + (size_t)(g - 1) * 65536; ldB = 512;
            bias = bias1 + (g - 1) * 128;
            j1 = p1[g - 1]; j2 = p2[g - 1];
        }
        Dh = g_out1h; ldO = 896; colO = g * 128;
    } else if (MODE == 1) {
        const int q1[6] = {0, 1, 1, 1, 4, 4};
        const int q2[6] = {1, 2, 3, 4, 5, 6};
        K = 256; Bsrc = g_W2h + (size_t)g * 32768; ldB = 256;
        bias = bias0 + g * 128;
        c1 = q1[g] * 128; c2 = q2[g] * 128;
        Ah = g_out1h; ldA = 896; Dh = g_out2h; ldO = 768; colO = g * 128;
    } else {
        K = 768; Bsrc = g_Wfh; ldB = 768; bias = bias0;
        Ah = g_out2h; ldA = 768; ldO = 256; colO = 0;
    }
    const int nk = K >> 5;

    float acc[4][8][4];
#pragma unroll
    for (int i = 0; i < 4; i++)
#pragma unroll
        for (int j = 0; j < 8; j++)
#pragma unroll
            for (int k = 0; k < 4; k++) acc[i][j][k] = 0.f;

    // ---- compute one 32-K chunk from smem stage ----
    auto compute = [&](int stage) {
        const uint32_t* Au = smu + stage * STG_U32;
        const uint32_t* Bu = Au + AM * 20;
#pragma unroll
        for (int s = 0; s < 2; s++) {
            const int o = 8 * s;
            unsigned a[4][4], b[8][2];
#pragma unroll
            for (int mt = 0; mt < 4; mt++) {
                const uint32_t* p = Au + (wm * 64 + mt * 16 + qr) * 20 + qc + o;
                a[mt][0] = p[0];
                a[mt][1] = p[160];
                a[mt][2] = p[4];
                a[mt][3] = p[164];
            }
#pragma unroll
            for (int nt = 0; nt < 8; nt++) {
                const uint32_t* p = Bu + (wn * 64 + nt * 8 + qr) * 20 + qc + o;
                b[nt][0] = p[0];
                b[nt][1] = p[4];
            }
#pragma unroll
            for (int mt = 0; mt < 4; mt++)
#pragma unroll
                for (int nt = 0; nt < 8; nt++) mma16(acc[mt][nt], a[mt], b[nt]);
        }
    };

    if (MODE == 0) {
        // -------- A: LDG fp32 -> cvt -> STS; B: cp.async; 2 stages --------
        float4 ar[8];
        auto ldgA = [&](int ci) {
            const int k0 = ci * 32;
            const int joff =
                (g == 0) ? k0 : (((k0 < 256) ? j1 : j2) * 256 + (k0 & 255));
#pragma unroll
            for (int u = 0; u < 8; u++) {
                const int idx = tid + u * 256, row = idx >> 3, seg = idx & 7;
                int r = row0 + row;
                if (r > N - 1) r = N - 1;
                ar[u] = *(const float4*)(Aupd + (size_t)r * 4352 + joff + seg * 4);
            }
        };
        auto stsA = [&](int stage) {
            const uint32_t base = smb + (uint32_t)stage * STG_BYTES;
#pragma unroll
            for (int u = 0; u < 8; u++) {
                const int idx = tid + u * 256, row = idx >> 3, seg = idx & 7;
                sts64(base + (uint32_t)(row * 20 + seg * 2) * 4,
                      packh(ar[u].y, ar[u].x), packh(ar[u].w, ar[u].z));
            }
        };
        auto cpB = [&](int ci, int stage) {
            const int k0 = ci * 32;
            const uint32_t Bb = smb + (uint32_t)stage * STG_BYTES + AM * 80;
#pragma unroll
            for (int u = 0; u < 2; u++) {
                const int idx = tid + u * 256, row = idx >> 2, gs = idx & 3;
                cpa_cg(Bb + (uint32_t)(row * 20 + gs * 4) * 4,
                       Bsrc + (size_t)row * ldB + k0 + gs * 8);
            }
            cp_commit();
        };

        ldgA(0); stsA(0); cpB(0, 0);
        ldgA(1);
        for (int i = 0; i < nk; i++) {
            cp_wait(0);
            __syncthreads();
            if (i + 1 < nk) { stsA((i + 1) & 1); cpB(i + 1, (i + 1) & 1); }
            if (i + 2 < nk) ldgA(i + 2);
            compute(i & 1);
        }
    } else {
        // -------- A and B both fp16 via cp.async; 4-stage ring --------
        constexpr int AG = AM / 64, BG = BN / 64;
        auto issue = [&](int ci) {
            const int k0 = ci * 32, stage = ci & 3;
            const uint32_t Abp = smb + (uint32_t)stage * STG_BYTES;
            const uint32_t Bbp = Abp + AM * 80;
            const int joff =
                (MODE == 1) ? ((k0 < 128) ? (c1 + k0) : (c2 + k0 - 128)) : k0;
#pragma unroll
            for (int u = 0; u < AG; u++) {
                const int idx = tid + u * 256, row = idx >> 2, gs = idx & 3;
                cpa_cg(Abp + (uint32_t)(row * 20 + gs * 4) * 4,
                       Ah + (size_t)(row0 + row) * ldA + joff + gs * 8);
            }
#pragma unroll
            for (int u = 0; u < BG; u++) {
                const int idx = tid + u * 256, row = idx >> 2, gs = idx & 3;
                cpa_cg(Bbp + (uint32_t)(row * 20 + gs * 4) * 4,
                       Bsrc + (size_t)row * ldB + k0 + gs * 8);
            }
            cp_commit();
        };

        issue(0); issue(1); issue(2);
        for (int i = 0; i < nk; i++) {
            const int rem = nk - 1 - i;
            cp_wait(rem < 2 ? rem : 2);
            __syncthreads();
            if (i + 3 < nk) issue(i + 3);
            compute(i & 3);
        }
    }

    // ---- epilogue: bias + relu ----
#pragma unroll
    for (int mt = 0; mt < 4; mt++) {
        const int r0 = row0 + wm * 64 + mt * 16 + qr;
#pragma unroll
        for (int nt = 0; nt < 8; nt++) {
            const int lc = wn * 64 + nt * 8 + 2 * qc;
            const float bb0 = __ldg(bias + lc);
            const float bb1 = __ldg(bias + lc + 1);
            const float v0 = fmaxf(acc[mt][nt][0] + bb0, 0.f);
            const float v1 = fmaxf(acc[mt][nt][1] + bb1, 0.f);
            const float v2 = fmaxf(acc[mt][nt][2] + bb0, 0.f);
            const float v3 = fmaxf(acc[mt][nt][3] + bb1, 0.f);
            if (MODE < 2) {
                if (r0 < N)
                    *(uint32_t*)&Dh[(size_t)r0 * ldO + colO + lc] = packh(v1, v0);
                if (r0 + 8 < N)
                    *(uint32_t*)&Dh[(size_t)(r0 + 8) * ldO + colO + lc] =
                        packh(v3, v2);
            } else {
                if (r0 < N)
                    *(float2*)&outp[(size_t)r0 * 256 + lc] = make_float2(v0, v1);
                if (r0 + 8 < N)
                    *(float2*)&outp[(size_t)(r0 + 8) * 256 + lc] =
                        make_float2(v2, v3);
            }
        }
    }
}

// ---------------------------------------------------------------------------
extern "C" void kernel_launch(void* const* d_in, const int* in_sizes, int n_in,
                              void* d_out, int out_size) {
    const float* upd = (const float*)d_in[0];
    const float* W10 = (const float*)d_in[1];
    const float* b10 = (const float*)d_in[2];
    const float* W1  = (const float*)d_in[3];
    const float* b1  = (const float*)d_in[4];
    const float* W2  = (const float*)d_in[5];
    const float* b2  = (const float*)d_in[6];
    const float* Wf  = (const float*)d_in[7];
    const float* bf  = (const float*)d_in[8];
    const int N = in_sizes[0] / (17 * 256);

    const int smem = 4 * STG_BYTES;  // 122880 B
    cudaFuncSetAttribute(gemm_h<0>, cudaFuncAttributeMaxDynamicSharedMemorySize, smem);
    cudaFuncSetAttribute(gemm_h<1>, cudaFuncAttributeMaxDynamicSharedMemorySize, smem);
    cudaFuncSetAttribute(gemm_h<2>, cudaFuncAttributeMaxDynamicSharedMemorySize, smem);

    cvt_weights<<<256, 256>>>(W10, W1, W2, Wf);

    const int t256 = (N + 255) / 256;
    const int t128 = (N + 127) / 128;
    gemm_h<0><<<dim3(t256, 7), 256, smem>>>(upd, b10, b1, nullptr, N);
    gemm_h<1><<<dim3(t256, 6), 256, smem>>>(nullptr, b2, nullptr, nullptr, N);
    gemm_h<2><<<dim3(t128, 1), 256, smem>>>(nullptr, bf, nullptr, (float*)d_out, N);
}